// round 13
// baseline (speedup 1.0000x reference)
#include <cuda_runtime.h>
#include <cuda_fp16.h>
#include <cstdint>

// Problem constants
#define NHEAD   8
#define DK      64
#define LEN     100
#define BS      32
#define DMODEL  512
#define TEMP    20.0f
#define LN8192  9.0109133f
#define RSCALE  32.0f          // residual scale for 2-mma exact-ish S
#define RINV    0.03125f       // 1/32

// Q: FRAGMENT-ORDER image per (b,h): word idx = (fs*4+ks)*128 + lane*4+u,
//    fs = row/16 (0..7). u: 0=(row g) 1=(row g+8) 2=(row g,w+4) 3=(row g+8,w+4).
//    Unwritten words (rows>=100) stay zero (static init).
__device__ __align__(16) uint32_t g_Qh[BS * NHEAD * 4096];
__device__ __align__(16) uint32_t g_Qx[BS * NHEAD * 4096];
// K: row-major image per (b,h): [128 rows][32 words]. Rows 100..127 zero.
__device__ __align__(16) uint32_t g_Kh[BS * NHEAD * 4096];
__device__ __align__(16) uint32_t g_Kx[BS * NHEAD * 4096];
// V: FRAGMENT-ORDER image per (kb,h): word idx = ((jv*7)+ks)*64 + lane*2 + u.
__device__ __align__(16) uint32_t g_Vf[BS * NHEAD * 3584];

// ---------------------------------------------------------------------------
__device__ __forceinline__ void mma_f16(float c[4],
    uint32_t a0, uint32_t a1, uint32_t a2, uint32_t a3,
    uint32_t b0, uint32_t b1)
{
    asm volatile(
        "mma.sync.aligned.m16n8k16.row.col.f32.f16.f16.f32 "
        "{%0,%1,%2,%3}, {%4,%5,%6,%7}, {%8,%9}, {%0,%1,%2,%3};"
        : "+f"(c[0]), "+f"(c[1]), "+f"(c[2]), "+f"(c[3])
        : "r"(a0), "r"(a1), "r"(a2), "r"(a3), "r"(b0), "r"(b1));
}

__device__ __forceinline__ void split2h(float x0, float x1,
                                        uint32_t& hi, uint32_t& lo)
{
    __half2 h = __floats2half2_rn(x0, x1);
    float2 hf = __half22float2(h);
    __half2 l = __floats2half2_rn(x0 - hf.x, x1 - hf.y);
    hi = *(uint32_t*)&h;
    lo = *(uint32_t*)&l;
}

// h = fp16(y), x = fp16(h + 32*(y-h))  (scaled-residual pair)
__device__ __forceinline__ void splitrx(float y0, float y1,
                                        uint32_t& hw, uint32_t& xw)
{
    __half2 h = __floats2half2_rn(y0, y1);
    float2 hf = __half22float2(h);
    __half2 x = __floats2half2_rn(fmaf(RSCALE, y0 - hf.x, hf.x),
                                  fmaf(RSCALE, y1 - hf.y, hf.y));
    hw = *(uint32_t*)&h;
    xw = *(uint32_t*)&x;
}

// ---------------------------------------------------------------------------
// Kernel 1: projection (z=0: Q frag-order out; z=1: K row-major out) +
//           z=2 slice: V^T frag-order image builder. (unchanged, 59us)
// ---------------------------------------------------------------------------
#define PJ_AHI 0
#define PJ_ALO 16128
#define PJ_BHI 32256
#define PJ_BLO 41472
#define PJ_SMEM 50688

__global__ __launch_bounds__(256) void proj_kernel(
    const float* __restrict__ q, const float* __restrict__ k,
    const float* __restrict__ w_qs, const float* __restrict__ w_ks,
    const float* __restrict__ v)
{
    const int tid = threadIdx.x;

    // ---- z == 2: V^T frag-order image, one (kb,h) per (x,y) block
    if (blockIdx.z == 2) {
        const int bh = blockIdx.y * 8 + blockIdx.x;
        const float* vp = v + (size_t)(bh >> 3) * 51200 + (bh & 7) * 6400;
        uint32_t* VF = g_Vf + (size_t)bh * 3584;
        for (int e = tid; e < 3584; e += 256) {
            const int d = e / 56, p = e % 56;          // dv col, m-pair
            const int m0 = 2 * p, m1 = 2 * p + 1;
            float x0 = (m0 < LEN) ? vp[m0 * 64 + d] : 0.0f;
            float x1 = (m1 < LEN) ? vp[m1 * 64 + d] : 0.0f;
            __half2 hv = __floats2half2_rn(x0, x1);
            const int ks = p >> 3, uh = (p >> 2) & 1, t = p & 3;
            const int jv = d >> 3, g = d & 7;
            VF[((jv * 7) + ks) * 64 + (g * 4 + t) * 2 + uh] = *(uint32_t*)&hv;
        }
        return;
    }

    extern __shared__ char sm[];
    uint32_t* AHI = (uint32_t*)(sm + PJ_AHI);
    uint32_t* ALO = (uint32_t*)(sm + PJ_ALO);
    uint32_t* BHI = (uint32_t*)(sm + PJ_BHI);
    uint32_t* BLO = (uint32_t*)(sm + PJ_BLO);
    float* S = (float*)sm;

    const int cb = blockIdx.x, b = blockIdx.y, sel = blockIdx.z;
    const float* x = sel ? k : q;
    const float* w = sel ? w_ks : w_qs;

    const int warp = tid >> 5, lane = tid & 31;
    const int g = lane >> 2, t = lane & 3;

    float4 pa[7], pb[4];

    #pragma unroll
    for (int u = 0; u < 7; u++) {
        const int i = tid + 256 * u, r = i >> 4, c4 = i & 15;
        pa[u] = (r < LEN)
            ? *(const float4*)(x + (size_t)(b * 100 + r) * DMODEL + c4 * 4)
            : make_float4(0.f, 0.f, 0.f, 0.f);
    }
    #pragma unroll
    for (int u = 0; u < 4; u++) {
        const int i = tid + 256 * u, r = i >> 4, c4 = i & 15;
        pb[u] = *(const float4*)(w + (size_t)(cb * 64 + r) * DMODEL + c4 * 4);
    }

    float acc[7][4] = {};

    for (int c = 0; c < 8; c++) {
        __syncthreads();
        #pragma unroll
        for (int u = 0; u < 7; u++) {
            const int i = tid + 256 * u, r = i >> 4, c4 = i & 15;
            uint32_t h0, l0, h1, l1;
            split2h(pa[u].x, pa[u].y, h0, l0);
            split2h(pa[u].z, pa[u].w, h1, l1);
            AHI[r * 36 + c4 * 2] = h0; AHI[r * 36 + c4 * 2 + 1] = h1;
            ALO[r * 36 + c4 * 2] = l0; ALO[r * 36 + c4 * 2 + 1] = l1;
        }
        #pragma unroll
        for (int u = 0; u < 4; u++) {
            const int i = tid + 256 * u, r = i >> 4, c4 = i & 15;
            uint32_t h0, l0, h1, l1;
            split2h(pb[u].x, pb[u].y, h0, l0);
            split2h(pb[u].z, pb[u].w, h1, l1);
            BHI[r * 36 + c4 * 2] = h0; BHI[r * 36 + c4 * 2 + 1] = h1;
            BLO[r * 36 + c4 * 2] = l0; BLO[r * 36 + c4 * 2 + 1] = l1;
        }
        __syncthreads();
        if (c < 7) {
            const int k0 = (c + 1) * 64;
            #pragma unroll
            for (int u = 0; u < 7; u++) {
                const int i = tid + 256 * u, r = i >> 4, c4 = i & 15;
                pa[u] = (r < LEN)
                    ? *(const float4*)(x + (size_t)(b * 100 + r) * DMODEL + k0 + c4 * 4)
                    : make_float4(0.f, 0.f, 0.f, 0.f);
            }
            #pragma unroll
            for (int u = 0; u < 4; u++) {
                const int i = tid + 256 * u, r = i >> 4, c4 = i & 15;
                pb[u] = *(const float4*)(w + (size_t)(cb * 64 + r) * DMODEL + k0 + c4 * 4);
            }
        }
        #pragma unroll
        for (int ks = 0; ks < 4; ks++) {
            const int nb = (warp * 8 + g) * 36 + ks * 8 + t;
            const uint32_t bh0 = BHI[nb], bh1 = BHI[nb + 4];
            const uint32_t bl0 = BLO[nb], bl1 = BLO[nb + 4];
            #pragma unroll
            for (int i = 0; i < 7; i++) {
                const int rb = (i * 16 + g) * 36 + ks * 8 + t;
                const uint32_t ah0 = AHI[rb], ah1 = AHI[rb + 288];
                const uint32_t ah2 = AHI[rb + 4], ah3 = AHI[rb + 292];
                const uint32_t al0 = ALO[rb], al1 = ALO[rb + 288];
                const uint32_t al2 = ALO[rb + 4], al3 = ALO[rb + 292];
                mma_f16(acc[i], ah0, ah1, ah2, ah3, bh0, bh1);
                mma_f16(acc[i], ah0, ah1, ah2, ah3, bl0, bl1);
                mma_f16(acc[i], al0, al1, al2, al3, bh0, bh1);
            }
        }
    }
    __syncthreads();

    #pragma unroll
    for (int i = 0; i < 7; i++) {
        const int cc = warp * 8 + 2 * t;
        *(float2*)(S + (i * 16 + g) * 68 + cc)     = make_float2(acc[i][0], acc[i][1]);
        *(float2*)(S + (i * 16 + g + 8) * 68 + cc) = make_float2(acc[i][2], acc[i][3]);
    }
    __syncthreads();

    // normalize slab row tid (<100) = raw-view chunk n = tid*8 + cb.
    if (tid < LEN) {
        const float* Sr = S + tid * 68;
        float ss = 0.0f;
        #pragma unroll
        for (int u = 0; u < 16; u++) {
            float4 xv = *(const float4*)(Sr + u * 4);
            ss += xv.x * xv.x + xv.y * xv.y + xv.z * xv.z + xv.w * xv.w;
        }
        const float inv = 1.0f / fmaxf(sqrtf(ss), 1e-12f);
        const int n = tid * 8 + cb;
        const int hh = n / 100, ll = n % 100;
        if (sel == 0) {
            // Q: scatter into FRAGMENT-ORDER image
            uint32_t* GH = g_Qh + (size_t)(b * 8 + hh) * 4096;
            uint32_t* GX = g_Qx + (size_t)(b * 8 + hh) * 4096;
            const int fs = ll >> 4, rr = ll & 15;
            const int gbit = (rr >> 3) & 1, gg = rr & 7;
            #pragma unroll
            for (int w = 0; w < 32; w++) {
                float2 pv = *(const float2*)(Sr + 2 * w);
                uint32_t hw, xw;
                splitrx(pv.x * inv, pv.y * inv, hw, xw);
                const int ks = w >> 3, uh = (w >> 2) & 1, tt = w & 3;
                const int idx = (fs * 4 + ks) * 128
                              + (gg * 4 + tt) * 4 + gbit + 2 * uh;
                GH[idx] = hw; GX[idx] = xw;
            }
        } else {
            // K: row-major image
            uint32_t* GH = g_Kh + ((size_t)(b * 8 + hh) * 128 + ll) * 32;
            uint32_t* GX = g_Kx + ((size_t)(b * 8 + hh) * 128 + ll) * 32;
            #pragma unroll
            for (int u = 0; u < 16; u++) {
                float4 xv = *(const float4*)(Sr + u * 4);
                uint32_t h0, x0, h1, x1;
                splitrx(xv.x * inv, xv.y * inv, h0, x0);
                splitrx(xv.z * inv, xv.w * inv, h1, x1);
                GH[u * 2] = h0; GH[u * 2 + 1] = h1;
                GX[u * 2] = x0; GX[u * 2 + 1] = x1;
            }
        }
    }
}

// ---------------------------------------------------------------------------
// Kernel 2: attention. M=64 half-blocks: one block per (qb,kb,h,half),
// grid 16384, 8 warps (wm = m16 strip 0..3, wn = N half 0..1), 3 CTAs/SM.
//   A-cache: LDG.128 from Q frag image (fs = half*4 + wm).
//   S[64x112] = Q K^T (2-mma scaled residual); per-j fused epilogue -> P fp16.
//   O[64x64]  = P V (V frags via LDG.64 from frag image).
// ---------------------------------------------------------------------------
#define OFF_RS   0                       // 64 rows x 2 floats = 512B
#define OFF_KH   512                     // 112 x 36 words = 16128B
#define OFF_KX   16640
#define OFF_P    32768                   // 64 x 60 words = 15360B
#define ATTN_SMEM 48128                  // -> 3 CTAs/SM (144KB)

__global__ __launch_bounds__(256, 3) void attn_kernel(float* __restrict__ out)
{
    extern __shared__ char sm[];
    float* RS = (float*)(sm + OFF_RS);
    uint32_t* KH = (uint32_t*)(sm + OFF_KH);
    uint32_t* KX = (uint32_t*)(sm + OFF_KX);
    uint32_t* P  = (uint32_t*)(sm + OFF_P);

    const int bx = blockIdx.x;
    const int h    = bx & 7;
    const int qb   = (bx >> 3) & 31;
    const int kb   = (bx >> 8) & 31;
    const int half = bx >> 13;
    const int tid = threadIdx.x;
    const int warp = tid >> 5, lane = tid & 31;
    const int g = lane >> 2, t = lane & 3;
    const int wm = warp & 3, wn = warp >> 2;
    const int fs = half * 4 + wm;            // global m16 strip 0..7
    const int c0 = wn * 56;

    // ---- A-cache: direct coalesced LDG.128 from frag-order Q image
    uint32_t ah[4][4], ax[4][4];
    {
        const uint4* qh4 = (const uint4*)(g_Qh + (size_t)(qb * 8 + h) * 4096);
        const uint4* qx4 = (const uint4*)(g_Qx + (size_t)(qb * 8 + h) * 4096);
        #pragma unroll
        for (int ks = 0; ks < 4; ks++) {
            const int idx = (fs * 4 + ks) * 32 + lane;   // uint4 units
            uint4 a = qh4[idx];
            ah[ks][0] = a.x; ah[ks][1] = a.y; ah[ks][2] = a.z; ah[ks][3] = a.w;
            uint4 b = qx4[idx];
            ax[ks][0] = b.x; ax[ks][1] = b.y; ax[ks][2] = b.z; ax[ks][3] = b.w;
        }
    }

    // ---- K staging: row-major gmem -> smem (stride 36 words)
    {
        const uint4* skh = (const uint4*)(g_Kh + (size_t)(kb * 8 + h) * 4096);
        const uint4* skx = (const uint4*)(g_Kx + (size_t)(kb * 8 + h) * 4096);
        uint4* dkh = (uint4*)KH; uint4* dkx = (uint4*)KX;
        for (int i = tid; i < 896; i += 256) {        // K: 112 rows x 8 uint4
            const int r = i >> 3, c = i & 7;
            const int s = r * 8 + c, d = r * 9 + c;
            dkh[d] = skh[s]; dkx[d] = skx[s];
        }
    }
    __syncthreads();

    // ---- S phase with per-j fused epilogue
    float rs0 = 0.f, rs1 = 0.f;
    #pragma unroll
    for (int j = 0; j < 7; j++) {
        const bool dead = (wn == 1 && j == 6);   // cols 104..111 fully masked
        float shh[4] = {}, sxy[4] = {};
        if (!dead) {
            #pragma unroll
            for (int ks = 0; ks < 4; ks++) {
                const int nb = (c0 + 8 * j + g) * 36 + ks * 8 + t;
                const uint32_t bh0 = KH[nb], bh1 = KH[nb + 4];
                const uint32_t bx0 = KX[nb], bx1 = KX[nb + 4];
                mma_f16(shh, ah[ks][0], ah[ks][1], ah[ks][2], ah[ks][3], bh0, bh1);
                mma_f16(sxy, ax[ks][0], ax[ks][1], ax[ks][2], ax[ks][3], bx0, bx1);
            }
        }
        const int col = c0 + 8 * j + 2 * t;
        float e[4];
        #pragma unroll
        for (int u = 0; u < 4; u++) {
            const float sf = fmaf(sxy[u] - shh[u], RINV, shh[u]);
            e[u] = __expf(fmaf(TEMP, fmaxf(sf, 0.0f), -LN8192));
        }
        if (dead)           { e[0] = e[1] = e[2] = e[3] = 0.f; }
        if (col >= LEN)     { e[0] = 0.f; e[2] = 0.f; }
        if (col + 1 >= LEN) { e[1] = 0.f; e[3] = 0.f; }
        rs0 += e[0] + e[1];
        rs1 += e[2] + e[3];
        __half2 h01 = __floats2half2_rn(e[0], e[1]);
        __half2 h23 = __floats2half2_rn(e[2], e[3]);
        const int w0 = (wm * 16 + g) * 60 + (c0 >> 1) + j * 4 + t;
        P[w0]       = *(uint32_t*)&h01;
        P[w0 + 480] = *(uint32_t*)&h23;
    }
    // rowsum reduction (width-4 k-group shuffle), 2 partials per row
    rs0 += __shfl_xor_sync(0xffffffffu, rs0, 1);
    rs0 += __shfl_xor_sync(0xffffffffu, rs0, 2);
    rs1 += __shfl_xor_sync(0xffffffffu, rs1, 1);
    rs1 += __shfl_xor_sync(0xffffffffu, rs1, 2);
    if (t == 0) {
        RS[(wm * 16 + g) * 2 + wn]     = rs0;
        RS[(wm * 16 + g + 8) * 2 + wn] = rs1;
    }
    __syncthreads();

    // ---- O phase: warp rows [wm*16,+16) x dv cols [wn*32,+32), K=112, 1-term
    const uint2* vf2 = (const uint2*)(g_Vf + (size_t)(kb * 8 + h) * 3584);
    float o[4][4] = {};
    #pragma unroll
    for (int ks = 0; ks < 7; ks++) {
        const int rb = (wm * 16 + g) * 60 + ks * 8 + t;
        const uint32_t a0 = P[rb],     a1 = P[rb + 480];
        const uint32_t a2 = P[rb + 4], a3 = P[rb + 484];
        #pragma unroll
        for (int j = 0; j < 4; j++) {
            const uint2 bv = vf2[((wn * 4 + j) * 7 + ks) * 32 + lane];
            mma_f16(o[j], a0, a1, a2, a3, bv.x, bv.y);
        }
    }

    // ---- output: divide by rowsum, write [kb][qb][l][h*64+d]
    const size_t ob = (size_t)(kb * 32 + qb) * LEN * DMODEL + h * 64;
    const int rg = half * 64 + wm * 16 + g;
    float inv0 = 0.f, inv1 = 0.f;
    const int rl = wm * 16 + g;
    if (rg < LEN)     inv0 = 1.0f / (RS[rl * 2] + RS[rl * 2 + 1]);
    if (rg + 8 < LEN) inv1 = 1.0f / (RS[(rl + 8) * 2] + RS[(rl + 8) * 2 + 1]);
    #pragma unroll
    for (int j = 0; j < 4; j++) {
        const int cc = wn * 32 + 8 * j + 2 * t;
        if (rg < LEN) {
            *(float2*)(out + ob + (size_t)rg * DMODEL + cc) =
                make_float2(o[j][0] * inv0, o[j][1] * inv0);
        }
        if (rg + 8 < LEN) {
            *(float2*)(out + ob + (size_t)(rg + 8) * DMODEL + cc) =
                make_float2(o[j][2] * inv1, o[j][3] * inv1);
        }
    }
}

// ---------------------------------------------------------------------------
extern "C" void kernel_launch(void* const* d_in, const int* in_sizes, int n_in,
                              void* d_out, int out_size)
{
    const float* q    = (const float*)d_in[0];
    const float* k    = (const float*)d_in[1];
    const float* v    = (const float*)d_in[2];
    const float* w_qs = (const float*)d_in[3];
    const float* w_ks = (const float*)d_in[4];
    float* out = (float*)d_out;

    cudaFuncSetAttribute(proj_kernel,
                         cudaFuncAttributeMaxDynamicSharedMemorySize, PJ_SMEM);
    cudaFuncSetAttribute(attn_kernel,
                         cudaFuncAttributeMaxDynamicSharedMemorySize, ATTN_SMEM);

    proj_kernel<<<dim3(8, 32, 3), 256, PJ_SMEM>>>(q, k, w_qs, w_ks, v);
    attn_kernel<<<16384, 256, ATTN_SMEM>>>(out);
}

// round 15
// speedup vs baseline: 1.1080x; 1.1080x over previous
#include <cuda_runtime.h>
#include <cuda_fp16.h>
#include <cstdint>

// Problem constants
#define NHEAD   8
#define DK      64
#define LEN     100
#define BS      32
#define DMODEL  512
#define TEMP    20.0f
#define LN8192  9.0109133f
#define RSCALE  32.0f          // residual scale for 2-mma exact-ish S
#define RINV    0.03125f       // 1/32

// Q: FRAGMENT-ORDER image per (b,h): word idx = (fs*4+ks)*128 + lane*4+u,
//    fs = row/16 (0..7). Unwritten words (rows>=100) stay zero (static init).
__device__ __align__(16) uint32_t g_Qh[BS * NHEAD * 4096];
__device__ __align__(16) uint32_t g_Qx[BS * NHEAD * 4096];
// K: FRAGMENT-ORDER B image per (b,h): word idx = (j*4+ks)*64 + lane*2 + u,
//    j = col/8 (0..13). Cols >= 100 stay zero.
__device__ __align__(16) uint32_t g_Kh[BS * NHEAD * 3584];
__device__ __align__(16) uint32_t g_Kx[BS * NHEAD * 3584];
// V: FRAGMENT-ORDER image per (kb,h): word idx = ((jv*7)+ks)*64 + lane*2 + u.
__device__ __align__(16) uint32_t g_Vf[BS * NHEAD * 3584];

// ---------------------------------------------------------------------------
__device__ __forceinline__ void mma_f16(float c[4],
    uint32_t a0, uint32_t a1, uint32_t a2, uint32_t a3,
    uint32_t b0, uint32_t b1)
{
    asm volatile(
        "mma.sync.aligned.m16n8k16.row.col.f32.f16.f16.f32 "
        "{%0,%1,%2,%3}, {%4,%5,%6,%7}, {%8,%9}, {%0,%1,%2,%3};"
        : "+f"(c[0]), "+f"(c[1]), "+f"(c[2]), "+f"(c[3])
        : "r"(a0), "r"(a1), "r"(a2), "r"(a3), "r"(b0), "r"(b1));
}

__device__ __forceinline__ void split2h(float x0, float x1,
                                        uint32_t& hi, uint32_t& lo)
{
    __half2 h = __floats2half2_rn(x0, x1);
    float2 hf = __half22float2(h);
    __half2 l = __floats2half2_rn(x0 - hf.x, x1 - hf.y);
    hi = *(uint32_t*)&h;
    lo = *(uint32_t*)&l;
}

// h = fp16(y), x = fp16(h + 32*(y-h))  (scaled-residual pair)
__device__ __forceinline__ void splitrx(float y0, float y1,
                                        uint32_t& hw, uint32_t& xw)
{
    __half2 h = __floats2half2_rn(y0, y1);
    float2 hf = __half22float2(h);
    __half2 x = __floats2half2_rn(fmaf(RSCALE, y0 - hf.x, hf.x),
                                  fmaf(RSCALE, y1 - hf.y, hf.y));
    hw = *(uint32_t*)&h;
    xw = *(uint32_t*)&x;
}

// ---------------------------------------------------------------------------
// Kernel 1: projection (z=0: Q frag-order; z=1: K frag-order B image) +
//           z=2 slice: V^T frag-order image builder.
// ---------------------------------------------------------------------------
#define PJ_AHI 0
#define PJ_ALO 16128
#define PJ_BHI 32256
#define PJ_BLO 41472
#define PJ_SMEM 50688

__global__ __launch_bounds__(256) void proj_kernel(
    const float* __restrict__ q, const float* __restrict__ k,
    const float* __restrict__ w_qs, const float* __restrict__ w_ks,
    const float* __restrict__ v)
{
    const int tid = threadIdx.x;

    // ---- z == 2: V^T frag-order image, one (kb,h) per (x,y) block
    if (blockIdx.z == 2) {
        const int bh = blockIdx.y * 8 + blockIdx.x;
        const float* vp = v + (size_t)(bh >> 3) * 51200 + (bh & 7) * 6400;
        uint32_t* VF = g_Vf + (size_t)bh * 3584;
        for (int e = tid; e < 3584; e += 256) {
            const int d = e / 56, p = e % 56;          // dv col, m-pair
            const int m0 = 2 * p, m1 = 2 * p + 1;
            float x0 = (m0 < LEN) ? vp[m0 * 64 + d] : 0.0f;
            float x1 = (m1 < LEN) ? vp[m1 * 64 + d] : 0.0f;
            __half2 hv = __floats2half2_rn(x0, x1);
            const int ks = p >> 3, uh = (p >> 2) & 1, t = p & 3;
            const int jv = d >> 3, g = d & 7;
            VF[((jv * 7) + ks) * 64 + (g * 4 + t) * 2 + uh] = *(uint32_t*)&hv;
        }
        return;
    }

    extern __shared__ char sm[];
    uint32_t* AHI = (uint32_t*)(sm + PJ_AHI);
    uint32_t* ALO = (uint32_t*)(sm + PJ_ALO);
    uint32_t* BHI = (uint32_t*)(sm + PJ_BHI);
    uint32_t* BLO = (uint32_t*)(sm + PJ_BLO);
    float* S = (float*)sm;

    const int cb = blockIdx.x, b = blockIdx.y, sel = blockIdx.z;
    const float* x = sel ? k : q;
    const float* w = sel ? w_ks : w_qs;

    const int warp = tid >> 5, lane = tid & 31;
    const int g = lane >> 2, t = lane & 3;

    float4 pa[7], pb[4];

    #pragma unroll
    for (int u = 0; u < 7; u++) {
        const int i = tid + 256 * u, r = i >> 4, c4 = i & 15;
        pa[u] = (r < LEN)
            ? *(const float4*)(x + (size_t)(b * 100 + r) * DMODEL + c4 * 4)
            : make_float4(0.f, 0.f, 0.f, 0.f);
    }
    #pragma unroll
    for (int u = 0; u < 4; u++) {
        const int i = tid + 256 * u, r = i >> 4, c4 = i & 15;
        pb[u] = *(const float4*)(w + (size_t)(cb * 64 + r) * DMODEL + c4 * 4);
    }

    float acc[7][4] = {};

    for (int c = 0; c < 8; c++) {
        __syncthreads();
        #pragma unroll
        for (int u = 0; u < 7; u++) {
            const int i = tid + 256 * u, r = i >> 4, c4 = i & 15;
            uint32_t h0, l0, h1, l1;
            split2h(pa[u].x, pa[u].y, h0, l0);
            split2h(pa[u].z, pa[u].w, h1, l1);
            AHI[r * 36 + c4 * 2] = h0; AHI[r * 36 + c4 * 2 + 1] = h1;
            ALO[r * 36 + c4 * 2] = l0; ALO[r * 36 + c4 * 2 + 1] = l1;
        }
        #pragma unroll
        for (int u = 0; u < 4; u++) {
            const int i = tid + 256 * u, r = i >> 4, c4 = i & 15;
            uint32_t h0, l0, h1, l1;
            split2h(pb[u].x, pb[u].y, h0, l0);
            split2h(pb[u].z, pb[u].w, h1, l1);
            BHI[r * 36 + c4 * 2] = h0; BHI[r * 36 + c4 * 2 + 1] = h1;
            BLO[r * 36 + c4 * 2] = l0; BLO[r * 36 + c4 * 2 + 1] = l1;
        }
        __syncthreads();
        if (c < 7) {
            const int k0 = (c + 1) * 64;
            #pragma unroll
            for (int u = 0; u < 7; u++) {
                const int i = tid + 256 * u, r = i >> 4, c4 = i & 15;
                pa[u] = (r < LEN)
                    ? *(const float4*)(x + (size_t)(b * 100 + r) * DMODEL + k0 + c4 * 4)
                    : make_float4(0.f, 0.f, 0.f, 0.f);
            }
            #pragma unroll
            for (int u = 0; u < 4; u++) {
                const int i = tid + 256 * u, r = i >> 4, c4 = i & 15;
                pb[u] = *(const float4*)(w + (size_t)(cb * 64 + r) * DMODEL + k0 + c4 * 4);
            }
        }
        #pragma unroll
        for (int ks = 0; ks < 4; ks++) {
            const int nb = (warp * 8 + g) * 36 + ks * 8 + t;
            const uint32_t bh0 = BHI[nb], bh1 = BHI[nb + 4];
            const uint32_t bl0 = BLO[nb], bl1 = BLO[nb + 4];
            #pragma unroll
            for (int i = 0; i < 7; i++) {
                const int rb = (i * 16 + g) * 36 + ks * 8 + t;
                const uint32_t ah0 = AHI[rb], ah1 = AHI[rb + 288];
                const uint32_t ah2 = AHI[rb + 4], ah3 = AHI[rb + 292];
                const uint32_t al0 = ALO[rb], al1 = ALO[rb + 288];
                const uint32_t al2 = ALO[rb + 4], al3 = ALO[rb + 292];
                mma_f16(acc[i], ah0, ah1, ah2, ah3, bh0, bh1);
                mma_f16(acc[i], ah0, ah1, ah2, ah3, bl0, bl1);
                mma_f16(acc[i], al0, al1, al2, al3, bh0, bh1);
            }
        }
    }
    __syncthreads();

    #pragma unroll
    for (int i = 0; i < 7; i++) {
        const int cc = warp * 8 + 2 * t;
        *(float2*)(S + (i * 16 + g) * 68 + cc)     = make_float2(acc[i][0], acc[i][1]);
        *(float2*)(S + (i * 16 + g + 8) * 68 + cc) = make_float2(acc[i][2], acc[i][3]);
    }
    __syncthreads();

    // normalize slab row tid (<100) = raw-view chunk n = tid*8 + cb.
    if (tid < LEN) {
        const float* Sr = S + tid * 68;
        float ss = 0.0f;
        #pragma unroll
        for (int u = 0; u < 16; u++) {
            float4 xv = *(const float4*)(Sr + u * 4);
            ss += xv.x * xv.x + xv.y * xv.y + xv.z * xv.z + xv.w * xv.w;
        }
        const float inv = 1.0f / fmaxf(sqrtf(ss), 1e-12f);
        const int n = tid * 8 + cb;
        const int hh = n / 100, ll = n % 100;
        if (sel == 0) {
            // Q: scatter into A frag-order image
            uint32_t* GH = g_Qh + (size_t)(b * 8 + hh) * 4096;
            uint32_t* GX = g_Qx + (size_t)(b * 8 + hh) * 4096;
            const int fsq = ll >> 4, rr = ll & 15;
            const int gbit = (rr >> 3) & 1, gg = rr & 7;
            #pragma unroll
            for (int w = 0; w < 32; w++) {
                float2 pv = *(const float2*)(Sr + 2 * w);
                uint32_t hw, xw;
                splitrx(pv.x * inv, pv.y * inv, hw, xw);
                const int ks = w >> 3, uh = (w >> 2) & 1, tt = w & 3;
                const int idx = (fsq * 4 + ks) * 128
                              + (gg * 4 + tt) * 4 + gbit + 2 * uh;
                GH[idx] = hw; GX[idx] = xw;
            }
        } else {
            // K: scatter into B frag-order image (col = ll)
            uint32_t* GH = g_Kh + (size_t)(b * 8 + hh) * 3584;
            uint32_t* GX = g_Kx + (size_t)(b * 8 + hh) * 3584;
            const int jj = ll >> 3, gg = ll & 7;
            #pragma unroll
            for (int w = 0; w < 32; w++) {
                float2 pv = *(const float2*)(Sr + 2 * w);
                uint32_t hw, xw;
                splitrx(pv.x * inv, pv.y * inv, hw, xw);
                const int ks = w >> 3, uh = (w >> 2) & 1, tt = w & 3;
                const int idx = (jj * 4 + ks) * 64 + (gg * 4 + tt) * 2 + uh;
                GH[idx] = hw; GX[idx] = xw;
            }
        }
    }
}

// ---------------------------------------------------------------------------
// Kernel 2: attention per (qb,kb,h), 8 warps, M=128 tile (round-12 shape).
//   A-cache: LDG.128 from Q frag image. B-frags: LDG.64 from K frag image,
//   software-pipelined (next-j prefetch during current-j mma). NO K smem,
//   NO staging barrier. Smem = P + RS only. S/O phases separated by a
//   64-thread NAMED barrier per wm pair (warps wm, wm+4).
// ---------------------------------------------------------------------------
#define OFF_RS   0                       // 128 rows x 2 floats = 1024B
#define OFF_P    1024                    // 128 x 60 words = 30720B
#define ATTN_SMEM 31744                  // -> 2 CTAs/SM easily

__global__ __launch_bounds__(256, 2) void attn_kernel(float* __restrict__ out)
{
    extern __shared__ char sm[];
    float* RS = (float*)(sm + OFF_RS);
    uint32_t* P  = (uint32_t*)(sm + OFF_P);

    const int bx = blockIdx.x;
    const int h  = bx & 7;
    const int qb = (bx >> 3) & 31;
    const int kb = bx >> 8;
    const int tid = threadIdx.x;
    const int warp = tid >> 5, lane = tid & 31;
    const int g = lane >> 2, t = lane & 3;
    const int wm = warp & 3, wn = warp >> 2;
    const int r0 = wm * 32;
    const int c0 = wn * 56;
    const int j0 = wn * 7;               // global j strip base

    // ---- A-cache: direct coalesced LDG.128 from frag-order Q image
    uint32_t ah[2][4][4], ax[2][4][4];
    {
        const uint4* qh4 = (const uint4*)(g_Qh + (size_t)(qb * 8 + h) * 4096);
        const uint4* qx4 = (const uint4*)(g_Qx + (size_t)(qb * 8 + h) * 4096);
        #pragma unroll
        for (int i = 0; i < 2; i++) {
            #pragma unroll
            for (int ks = 0; ks < 4; ks++) {
                const int idx = ((wm * 2 + i) * 4 + ks) * 32 + lane;
                uint4 a = qh4[idx];
                ah[i][ks][0] = a.x; ah[i][ks][1] = a.y;
                ah[i][ks][2] = a.z; ah[i][ks][3] = a.w;
                uint4 b = qx4[idx];
                ax[i][ks][0] = b.x; ax[i][ks][1] = b.y;
                ax[i][ks][2] = b.z; ax[i][ks][3] = b.w;
            }
        }
    }

    // ---- K frag pointers + preload j=0
    const uint2* KH2 = (const uint2*)(g_Kh + (size_t)(kb * 8 + h) * 3584);
    const uint2* KX2 = (const uint2*)(g_Kx + (size_t)(kb * 8 + h) * 3584);
    uint2 bh[4], bxv[4];
    #pragma unroll
    for (int ks = 0; ks < 4; ks++) {
        bh[ks]  = KH2[(j0 * 4 + ks) * 32 + lane];
        bxv[ks] = KX2[(j0 * 4 + ks) * 32 + lane];
    }

    // ---- S phase, pipelined over j; per-j fused epilogue
    // (cols >= 100 are statically zero in the K image -> no dead branch;
    //  the col mask below zeroes their exp contribution.)
    float rs[2][2] = {{0.f, 0.f}, {0.f, 0.f}};
    #pragma unroll
    for (int j = 0; j < 7; j++) {
        uint2 nh[4], nx[4];
        if (j < 6) {
            #pragma unroll
            for (int ks = 0; ks < 4; ks++) {
                nh[ks] = KH2[((j0 + j + 1) * 4 + ks) * 32 + lane];
                nx[ks] = KX2[((j0 + j + 1) * 4 + ks) * 32 + lane];
            }
        }
        float shh[2][4] = {}, sxy[2][4] = {};
        #pragma unroll
        for (int ks = 0; ks < 4; ks++) {
            #pragma unroll
            for (int i = 0; i < 2; i++) {
                mma_f16(shh[i], ah[i][ks][0], ah[i][ks][1], ah[i][ks][2], ah[i][ks][3],
                        bh[ks].x, bh[ks].y);
                mma_f16(sxy[i], ax[i][ks][0], ax[i][ks][1], ax[i][ks][2], ax[i][ks][3],
                        bxv[ks].x, bxv[ks].y);
            }
        }
        const int col = c0 + 8 * j + 2 * t;
        #pragma unroll
        for (int i = 0; i < 2; i++) {
            float e[4];
            #pragma unroll
            for (int u = 0; u < 4; u++) {
                const float sf = fmaf(sxy[i][u] - shh[i][u], RINV, shh[i][u]);
                e[u] = __expf(fmaf(TEMP, fmaxf(sf, 0.0f), -LN8192));
            }
            if (col >= LEN)     { e[0] = 0.f; e[2] = 0.f; }
            if (col + 1 >= LEN) { e[1] = 0.f; e[3] = 0.f; }
            rs[i][0] += e[0] + e[1];
            rs[i][1] += e[2] + e[3];
            __half2 h01 = __floats2half2_rn(e[0], e[1]);
            __half2 h23 = __floats2half2_rn(e[2], e[3]);
            const int w0 = (r0 + 16 * i + g) * 60 + (c0 >> 1) + j * 4 + t;
            P[w0]       = *(uint32_t*)&h01;
            P[w0 + 480] = *(uint32_t*)&h23;
        }
        if (j < 6) {
            #pragma unroll
            for (int ks = 0; ks < 4; ks++) { bh[ks] = nh[ks]; bxv[ks] = nx[ks]; }
        }
    }
    // rowsum reduction (width-4 k-group shuffle), 2 partials per row
    #pragma unroll
    for (int i = 0; i < 2; i++) {
        rs[i][0] += __shfl_xor_sync(0xffffffffu, rs[i][0], 1);
        rs[i][0] += __shfl_xor_sync(0xffffffffu, rs[i][0], 2);
        rs[i][1] += __shfl_xor_sync(0xffffffffu, rs[i][1], 1);
        rs[i][1] += __shfl_xor_sync(0xffffffffu, rs[i][1], 2);
        if (t == 0) {
            RS[(r0 + 16 * i + g) * 2 + wn]     = rs[i][0];
            RS[(r0 + 16 * i + g + 8) * 2 + wn] = rs[i][1];
        }
    }

    // ---- named barrier: only warps (wm, wn=0) and (wm, wn=1) must meet
    asm volatile("bar.sync %0, %1;" :: "r"(wm + 1), "r"(64) : "memory");

    // ---- O phase: warp rows [r0,r0+32) x dv cols [wn*32,+32), K=112, 1-term
    const uint2* vf2 = (const uint2*)(g_Vf + (size_t)(kb * 8 + h) * 3584);
    float o[2][4][4] = {};
    #pragma unroll
    for (int ks = 0; ks < 7; ks++) {
        uint32_t a[2][4];
        #pragma unroll
        for (int i = 0; i < 2; i++) {
            const int rb = (r0 + 16 * i + g) * 60 + ks * 8 + t;
            a[i][0] = P[rb];        a[i][1] = P[rb + 480];
            a[i][2] = P[rb + 4];    a[i][3] = P[rb + 484];
        }
        #pragma unroll
        for (int j = 0; j < 4; j++) {
            const uint2 bv = vf2[((wn * 4 + j) * 7 + ks) * 32 + lane];
            #pragma unroll
            for (int i = 0; i < 2; i++) {
                mma_f16(o[i][j], a[i][0], a[i][1], a[i][2], a[i][3], bv.x, bv.y);
            }
        }
    }

    // ---- output: divide by rowsum, write [kb][qb][l][h*64+d]
    const size_t ob = (size_t)(kb * 32 + qb) * LEN * DMODEL + h * 64;
    #pragma unroll
    for (int i = 0; i < 2; i++) {
        const int r = r0 + 16 * i + g;
        float inv0 = 0.f, inv1 = 0.f;
        if (r < LEN)     inv0 = 1.0f / (RS[r * 2] + RS[r * 2 + 1]);
        if (r + 8 < LEN) inv1 = 1.0f / (RS[(r + 8) * 2] + RS[(r + 8) * 2 + 1]);
        #pragma unroll
        for (int j = 0; j < 4; j++) {
            const int cc = wn * 32 + 8 * j + 2 * t;
            if (r < LEN) {
                *(float2*)(out + ob + (size_t)r * DMODEL + cc) =
                    make_float2(o[i][j][0] * inv0, o[i][j][1] * inv0);
            }
            if (r + 8 < LEN) {
                *(float2*)(out + ob + (size_t)(r + 8) * DMODEL + cc) =
                    make_float2(o[i][j][2] * inv1, o[i][j][3] * inv1);
            }
        }
    }
}

// ---------------------------------------------------------------------------
extern "C" void kernel_launch(void* const* d_in, const int* in_sizes, int n_in,
                              void* d_out, int out_size)
{
    const float* q    = (const float*)d_in[0];
    const float* k    = (const float*)d_in[1];
    const float* v    = (const float*)d_in[2];
    const float* w_qs = (const float*)d_in[3];
    const float* w_ks = (const float*)d_in[4];
    float* out = (float*)d_out;

    cudaFuncSetAttribute(proj_kernel,
                         cudaFuncAttributeMaxDynamicSharedMemorySize, PJ_SMEM);
    cudaFuncSetAttribute(attn_kernel,
                         cudaFuncAttributeMaxDynamicSharedMemorySize, ATTN_SMEM);

    proj_kernel<<<dim3(8, 32, 3), 256, PJ_SMEM>>>(q, k, w_qs, w_ks, v);
    attn_kernel<<<8192, 256, ATTN_SMEM>>>(out);
}